// round 12
// baseline (speedup 1.0000x reference)
#include <cuda_runtime.h>
#include <cuda_fp16.h>
#include <cstdint>
#include <cstddef>

// ===========================================================================
// feature_embedding on GB300 (base compute_103: mma.sync fp16 tensor cores).
// Round 12: gate GEMM hoisted into its own kernel; epilogue shrunk to one
// small L2-hot GEMM + combine (4+ CTAs/SM); prep transpose rebuilt for MLP=4.
// gcn mainloop untouched (at the 1024 FMA/cyc/SM fallback-HMMA floor).
//  B=4, N=2048, DEST=64, NET=256, INPUT=448
// ===========================================================================

namespace {
constexpr int kB     = 4;
constexpr int kN     = 2048;
constexpr int kINPUT = 448;
constexpr int BM     = 128;
constexpr int BK     = 64;           // k per iter (4 x m16n8k16)
constexpr int SB     = 3;            // B cp.async stages
constexpr int NUM_K  = kN / BK;      // 32
constexpr int TILE_A16 = BM * BK * 2;            // 16 KB fp16 A tile
constexpr int TILE_B16 = 128 * BK * 2;           // 16 KB fp16 B tile
constexpr int A_REGION = 2 * TILE_A16;           // A double buffer 32 KB
constexpr int SMEM_GCN = A_REGION + SB * TILE_B16;   // 80 KB

// gate kernel smem (bytes)
constexpr int oS2  = 0;              // stat16  64 x 528B
constexpr int oWe2 = 33792;          // WeT    128 x 528B
constexpr int SMEM_GATE = 101376;

// epilogue v2 smem (bytes)
constexpr int oH  = 0;               // H16 tile 64 x 272B
constexpr int oWc = 17408;           // WcT      64 x 272B
constexpr int SMEM_EPI = 34816;
}

// scratch
__device__ __align__(1024) __half g_Bt    [(size_t)kB * 128 * kN];  // structT fp16
__device__ __align__(1024) __half g_H16   [(size_t)kB * kN * 256];  // [hf|hb] fp16
__device__ __align__(1024) __half g_stat16[(size_t)kB * kN * 256];  // stat fp16
__device__ __align__(1024) float  g_gate  [(size_t)kB * kN * 128];  // sigmoid(stat@We+be)
__device__ __align__(256)  __half g_WcT   [2 * 64 * 128];           // [mat][n][k]
__device__ __align__(256)  __half g_WeT   [128 * 256];              // [n][k]

// ---------------------------------------------------------------------------
// helpers
// ---------------------------------------------------------------------------
__device__ __forceinline__ uint32_t smem_u32(const void* p) {
    uint32_t a;
    asm("{ .reg .u64 t; cvta.to.shared.u64 t, %1; cvt.u32.u64 %0, t; }"
        : "=r"(a) : "l"(p));
    return a;
}
__device__ __forceinline__ void cp_async16(uint32_t dst, const void* src) {
    asm volatile("cp.async.cg.shared.global [%0], [%1], 16;"
                 :: "r"(dst), "l"(src) : "memory");
}
__device__ __forceinline__ void cp_commit() {
    asm volatile("cp.async.commit_group;" ::: "memory");
}
template <int N>
__device__ __forceinline__ void cp_wait() {
    asm volatile("cp.async.wait_group %0;" :: "n"(N) : "memory");
}
__device__ __forceinline__ uint32_t lds_u32(uint32_t addr) {
    uint32_t v;
    asm volatile("ld.shared.b32 %0, [%1];" : "=r"(v) : "r"(addr));
    return v;
}
__device__ __forceinline__ void ldsm_x4(uint32_t r[4], uint32_t addr) {
    asm volatile("ldmatrix.sync.aligned.m8n8.x4.shared.b16 {%0,%1,%2,%3}, [%4];"
                 : "=r"(r[0]), "=r"(r[1]), "=r"(r[2]), "=r"(r[3]) : "r"(addr));
}
__device__ __forceinline__ void sts_v4(uint32_t addr, uint32_t x, uint32_t y,
                                       uint32_t z, uint32_t w) {
    asm volatile("st.shared.v4.b32 [%0], {%1,%2,%3,%4};"
                 :: "r"(addr), "r"(x), "r"(y), "r"(z), "r"(w) : "memory");
}
__device__ __forceinline__ uint32_t pack_h2(float lo, float hi) {
    __half2 h = __floats2half2_rn(lo, hi);
    return *reinterpret_cast<uint32_t*>(&h);
}
__device__ __forceinline__ void mma_f16(float c[4], const uint32_t a[4],
                                        const uint32_t b[2]) {
    asm volatile(
        "mma.sync.aligned.m16n8k16.row.col.f32.f16.f16.f32 "
        "{%0,%1,%2,%3}, {%4,%5,%6,%7}, {%8,%9}, {%0,%1,%2,%3};"
        : "+f"(c[0]), "+f"(c[1]), "+f"(c[2]), "+f"(c[3])
        : "r"(a[0]), "r"(a[1]), "r"(a[2]), "r"(a[3]), "r"(b[0]), "r"(b[1]));
}

// ---------------------------------------------------------------------------
// Prep: blocks [0,256) transpose struct (MLP=4) -> g_Bt fp16;
//       blocks [256,768) convert stat + weights (already MLP=4).
// ---------------------------------------------------------------------------
__global__ void __launch_bounds__(256) prep_all(
    const float* __restrict__ nfeat,
    const float* __restrict__ Wf, const float* __restrict__ Wb,
    const float* __restrict__ We) {
    const int bx = blockIdx.x;
    const int tid = threadIdx.x;
    if (bx < 256) {
        // transpose tile: 128 nodes x 32 feats
        __shared__ float s[32][133];
        const int n0 = (bx & 15) * 128;
        const int f0 = ((bx >> 4) & 3) * 32;
        const int b  = bx >> 6;
        float4 x[4];
#pragma unroll
        for (int k = 0; k < 4; ++k) {        // 4 independent float4 loads (MLP=4)
            const int v = tid + 256 * k;     // 0..1023
            const int node = v >> 3;
            const int fq   = v & 7;
            x[k] = *(const float4*)(nfeat +
                (size_t)(b * kN + n0 + node) * kINPUT + 64 + f0 + fq * 4);
        }
#pragma unroll
        for (int k = 0; k < 4; ++k) {
            const int v = tid + 256 * k;
            const int node = v >> 3;
            const int fq   = v & 7;
            s[fq * 4 + 0][node] = x[k].x;
            s[fq * 4 + 1][node] = x[k].y;
            s[fq * 4 + 2][node] = x[k].z;
            s[fq * 4 + 3][node] = x[k].w;
        }
        __syncthreads();
#pragma unroll
        for (int j = 0; j < 4; ++j) {
            const int feat = (tid >> 5) + 8 * j;
            __half* dst = g_Bt + ((size_t)(b * 128 + f0 + feat)) * kN + n0;
#pragma unroll
            for (int cch = 0; cch < 4; ++cch) {
                const int node = (tid & 31) + 32 * cch;
                dst[node] = __float2half_rn(s[feat][node]);
            }
        }
    } else {
        const int t = (bx - 256) * 256 + tid;            // 0..131071
        for (int i = t; i < kB * kN * 64; i += 131072) { // stat fp32 -> fp16
            const int row = i >> 6, c4 = i & 63;
            const float4 v = *(const float4*)(nfeat + (size_t)row * kINPUT + 192 + c4 * 4);
            uint32_t* d = reinterpret_cast<uint32_t*>(g_stat16 + (size_t)row * 256 + c4 * 4);
            d[0] = pack_h2(v.x, v.y);
            d[1] = pack_h2(v.z, v.w);
        }
        if (t < 128 * 256) {      // WeT
            const int n = t >> 8, k = t & 255;
            g_WeT[t] = __float2half_rn(We[k * 128 + n]);
        }
        if (t < 64 * 128) {       // WcT (both mats)
            const int n = t >> 7, k = t & 127;
            g_WcT[t]        = __float2half_rn(Wf[k * 64 + n]);
            g_WcT[8192 + t] = __float2half_rn(Wb[k * 64 + n]);
        }
    }
}

// ---------------------------------------------------------------------------
// Gate kernel: g_gate[row][0:128] = sigmoid(stat16[row] @ WeT + be)
// grid 128 (64-row tiles); 256 threads; 2 CTAs/SM.
// ---------------------------------------------------------------------------
__global__ void __launch_bounds__(256, 2) gate_kernel(
    const float* __restrict__ be) {
    extern __shared__ char smem[];
    const uint32_t sb = smem_u32(smem);

    const int tid  = threadIdx.x;
    const int warp = tid >> 5;
    const int lane = tid & 31;
    const int lr   = lane >> 2;
    const int lc   = lane & 3;
    const int wm   = (warp >> 2) * 32;   // rows 0 | 32
    const int wn   = (warp & 3) * 32;    // cols 0 | 32 | 64 | 96

    const int r0 = blockIdx.x * 64;      // global row in [0, 8192)

    for (int idx = tid; idx < 2048; idx += 256) {        // stat16 64x256
        const int row = idx >> 5, v = idx & 31;
        cp_async16(sb + oS2 + row * 528 + v * 16,
                   g_stat16 + ((size_t)(r0 + row)) * 256 + v * 8);
    }
    for (int idx = tid; idx < 4096; idx += 256) {        // WeT 128x256
        const int row = idx >> 5, v = idx & 31;
        cp_async16(sb + oWe2 + row * 528 + v * 16,
                   g_WeT + ((size_t)row) * 256 + v * 8);
    }
    cp_commit();
    cp_wait<0>();
    __syncthreads();

    const uint32_t lcx = (uint32_t)(lc * 4);

    float c2[2][4][4];
#pragma unroll
    for (int mf = 0; mf < 2; ++mf)
#pragma unroll
        for (int nb = 0; nb < 4; ++nb)
#pragma unroll
            for (int r = 0; r < 4; ++r) c2[mf][nb][r] = 0.0f;
#pragma unroll
    for (int ks = 0; ks < 16; ++ks) {
        const uint32_t ko = (uint32_t)(ks * 32);
        uint32_t a[2][4];
#pragma unroll
        for (int mf = 0; mf < 2; ++mf) {
            const uint32_t ad = sb + oS2 + (uint32_t)((wm + mf * 16 + lr) * 528) + ko + lcx;
            a[mf][0] = lds_u32(ad);
            a[mf][1] = lds_u32(ad + 8 * 528);
            a[mf][2] = lds_u32(ad + 16);
            a[mf][3] = lds_u32(ad + 8 * 528 + 16);
        }
        uint32_t bf[4][2];
#pragma unroll
        for (int nb = 0; nb < 4; ++nb) {
            const uint32_t bd = sb + oWe2 + (uint32_t)((wn + nb * 8 + lr) * 528) + ko + lcx;
            bf[nb][0] = lds_u32(bd);
            bf[nb][1] = lds_u32(bd + 16);
        }
#pragma unroll
        for (int mf = 0; mf < 2; ++mf)
#pragma unroll
            for (int nb = 0; nb < 4; ++nb)
                mma_f16(c2[mf][nb], a[mf], bf[nb]);
    }

    // sigmoid + store fp32
#pragma unroll
    for (int nb = 0; nb < 4; ++nb) {
        const int cl = wn + nb * 8 + lc * 2;
        const float2 biasG = *(const float2*)(be + cl);
#pragma unroll
        for (int mf = 0; mf < 2; ++mf) {
#pragma unroll
            for (int h = 0; h < 2; ++h) {
                const int row = r0 + wm + mf * 16 + lr + h * 8;
                float2 o;
                o.x = 1.0f / (1.0f + __expf(-(c2[mf][nb][2 * h]     + biasG.x)));
                o.y = 1.0f / (1.0f + __expf(-(c2[mf][nb][2 * h + 1] + biasG.y)));
                *(float2*)(g_gate + (size_t)row * 128 + cl) = o;
            }
        }
    }
}

// ---------------------------------------------------------------------------
// Kernel A: H16-tile[128,128] = adj_tile[128,2048] @ structT[128,2048]^T
// (UNCHANGED — measured at the fallback-HMMA issue floor.)
// ---------------------------------------------------------------------------
__global__ void __launch_bounds__(256, 1) gcn_mma_kernel(
    const float* __restrict__ adjF, const float* __restrict__ adjB) {
    extern __shared__ char smem[];
    const uint32_t sbA = smem_u32(smem);
    const uint32_t sbB = sbA + A_REGION;

    const int tid  = threadIdx.x;
    const int warp = tid >> 5;
    const int lane = tid & 31;
    const int lr   = lane >> 2;
    const int lc   = lane & 3;
    const int wm   = (warp >> 2) * 64;
    const int wn   = (warp & 3) * 32;

    const int m0  = blockIdx.x * BM;
    const int b   = blockIdx.y;
    const int mat = blockIdx.z;
    const float* adj = mat ? adjB : adjF;

    const float*  srcA[4];
    const __half* srcB[4];
    uint32_t dstAB[4];
#pragma unroll
    for (int q = 0; q < 4; ++q) {
        const int idx = q * 256 + tid;
        const int row = idx >> 3;
        const int vec = idx & 7;
        srcA[q] = adj  + ((size_t)(b * kN + m0 + row)) * kN + vec * 8;
        srcB[q] = g_Bt + ((size_t)(b * 128 + row)) * kN + vec * 8;
        dstAB[q] = (uint32_t)(row * 128 + ((vec ^ (row & 7)) << 4));
    }

    const int g  = lane >> 3;
    const int tr = lane & 7;
    uint32_t aLdsm[4];
#pragma unroll
    for (int mf = 0; mf < 4; ++mf) {
        const int row = wm + mf * 16 + (g & 1) * 8 + tr;
        aLdsm[mf] = (uint32_t)(row * 128 + (((g >> 1) ^ (row & 7)) << 4));
    }
    uint32_t bLdsm[2];
#pragma unroll
    for (int p = 0; p < 2; ++p) {
        const int row = wn + p * 16 + (g >> 1) * 8 + tr;
        bLdsm[p] = (uint32_t)(row * 128 + (((g & 1) ^ (row & 7)) << 4));
    }

    float c[4][4][4];
#pragma unroll
    for (int mf = 0; mf < 4; ++mf)
#pragma unroll
        for (int nb = 0; nb < 4; ++nb)
#pragma unroll
            for (int r = 0; r < 4; ++r) c[mf][nb][r] = 0.0f;

#pragma unroll
    for (int s = 0; s < SB - 1; ++s) {
#pragma unroll
        for (int q = 0; q < 4; ++q)
            cp_async16(sbB + s * TILE_B16 + dstAB[q], srcB[q] + s * BK);
        cp_commit();
    }
    float4 rA[4][2];
#pragma unroll
    for (int q = 0; q < 4; ++q) {
        rA[q][0] = *(const float4*)(srcA[q]);
        rA[q][1] = *(const float4*)(srcA[q] + 4);
    }
#pragma unroll
    for (int q = 0; q < 4; ++q)
        sts_v4(sbA + dstAB[q],
               pack_h2(rA[q][0].x, rA[q][0].y), pack_h2(rA[q][0].z, rA[q][0].w),
               pack_h2(rA[q][1].x, rA[q][1].y), pack_h2(rA[q][1].z, rA[q][1].w));
#pragma unroll
    for (int q = 0; q < 4; ++q) {
        rA[q][0] = *(const float4*)(srcA[q] + BK);
        rA[q][1] = *(const float4*)(srcA[q] + BK + 4);
    }

    for (int i = 0; i < NUM_K; ++i) {
        cp_wait<SB - 2>();
        __syncthreads();

        if (i + 1 < NUM_K) {
            const uint32_t aNext = sbA + (uint32_t)(((i + 1) & 1) * TILE_A16);
#pragma unroll
            for (int q = 0; q < 4; ++q)
                sts_v4(aNext + dstAB[q],
                       pack_h2(rA[q][0].x, rA[q][0].y), pack_h2(rA[q][0].z, rA[q][0].w),
                       pack_h2(rA[q][1].x, rA[q][1].y), pack_h2(rA[q][1].z, rA[q][1].w));
        }
        if (i + 2 < NUM_K) {
            const int kof = (i + 2) * BK;
#pragma unroll
            for (int q = 0; q < 4; ++q) {
                rA[q][0] = *(const float4*)(srcA[q] + kof);
                rA[q][1] = *(const float4*)(srcA[q] + kof + 4);
            }
#pragma unroll
            for (int q = 0; q < 4; ++q)
                cp_async16(sbB + ((i + 2) % SB) * TILE_B16 + dstAB[q],
                           srcB[q] + kof);
        }
        cp_commit();

        const uint32_t aSlot = sbA + (uint32_t)((i & 1) * TILE_A16);
        const uint32_t bSlot = sbB + (uint32_t)((i % SB) * TILE_B16);
#pragma unroll
        for (int ks = 0; ks < 4; ++ks) {
            const uint32_t kx = (uint32_t)(ks << 5);
            uint32_t a[4][4];
#pragma unroll
            for (int mf = 0; mf < 4; ++mf)
                ldsm_x4(a[mf], (aSlot + aLdsm[mf]) ^ kx);
            uint32_t bf[4][4];
#pragma unroll
            for (int p = 0; p < 2; ++p)
                ldsm_x4(bf[p * 2], (bSlot + bLdsm[p]) ^ kx);
#pragma unroll
            for (int mf = 0; mf < 4; ++mf) {
#pragma unroll
                for (int p = 0; p < 2; ++p) {
                    mma_f16(c[mf][p * 2],     a[mf], &bf[p * 2][0]);
                    mma_f16(c[mf][p * 2 + 1], a[mf], &bf[p * 2][2]);
                }
            }
        }
    }

#pragma unroll
    for (int mf = 0; mf < 4; ++mf) {
        const int row = m0 + wm + mf * 16 + lr;
        const size_t base = ((size_t)(b * kN + row)) * 256 + mat * 128;
#pragma unroll
        for (int nb = 0; nb < 4; ++nb) {
            const int col = wn + nb * 8 + lc * 2;
            *reinterpret_cast<uint32_t*>(g_H16 + base + col) =
                pack_h2(c[mf][nb][0], c[mf][nb][1]);
            *reinterpret_cast<uint32_t*>(g_H16 + base + 8 * 256 + col) =
                pack_h2(c[mf][nb][2], c[mf][nb][3]);
        }
    }
}

// ---------------------------------------------------------------------------
// Epilogue v2: grid (128, 2) = (row-tile of 64, mat); 256 threads; 4+ CTAs/SM.
//   code = H16[:,mat*128:+128] @ WcT[mat]   (K=128, all tiles L2-hot)
//   out[:, mat*64:+64] = (code + bias) * dyn * g_gate (direct LDG)
// ---------------------------------------------------------------------------
__global__ void __launch_bounds__(256, 4) epilogue_mma(
    const float* __restrict__ nfeat,
    const float* __restrict__ bfv, const float* __restrict__ bbv,
    float* __restrict__ out) {
    extern __shared__ char smem[];
    const uint32_t sb = smem_u32(smem);

    const int tid  = threadIdx.x;
    const int warp = tid >> 5;
    const int lane = tid & 31;
    const int lr   = lane >> 2;
    const int lc   = lane & 3;
    const int wm   = (warp >> 2) * 32;   // rows 0 | 32
    const int wn   = (warp & 3) * 16;    // cols (0..63)

    const int r0  = blockIdx.x * 64;
    const int mat = blockIdx.y;

    for (int idx = tid; idx < 1024; idx += 256) {        // H16 slice 64x128
        const int row = idx >> 4, v = idx & 15;
        cp_async16(sb + oH + row * 272 + v * 16,
                   g_H16 + ((size_t)(r0 + row)) * 256 + mat * 128 + v * 8);
    }
    for (int idx = tid; idx < 1024; idx += 256) {        // WcT 64x128
        const int row = idx >> 4, v = idx & 15;
        cp_async16(sb + oWc + row * 272 + v * 16,
                   g_WcT + mat * 64 * 128 + row * 128 + v * 8);
    }
    cp_commit();
    cp_wait<0>();
    __syncthreads();

    const uint32_t lcx = (uint32_t)(lc * 4);

    float c1[2][2][4];
#pragma unroll
    for (int mf = 0; mf < 2; ++mf)
#pragma unroll
        for (int nb = 0; nb < 2; ++nb)
#pragma unroll
            for (int r = 0; r < 4; ++r) c1[mf][nb][r] = 0.0f;
#pragma unroll
    for (int ks = 0; ks < 8; ++ks) {
        const uint32_t ko = (uint32_t)(ks * 32);
        uint32_t a[2][4];
#pragma unroll
        for (int mf = 0; mf < 2; ++mf) {
            const uint32_t ad = sb + oH + (uint32_t)((wm + mf * 16 + lr) * 272) + ko + lcx;
            a[mf][0] = lds_u32(ad);
            a[mf][1] = lds_u32(ad + 8 * 272);
            a[mf][2] = lds_u32(ad + 16);
            a[mf][3] = lds_u32(ad + 8 * 272 + 16);
        }
        uint32_t bf[2][2];
#pragma unroll
        for (int nb = 0; nb < 2; ++nb) {
            const uint32_t bd = sb + oWc + (uint32_t)((wn + nb * 8 + lr) * 272) + ko + lcx;
            bf[nb][0] = lds_u32(bd);
            bf[nb][1] = lds_u32(bd + 16);
        }
#pragma unroll
        for (int mf = 0; mf < 2; ++mf)
#pragma unroll
            for (int nb = 0; nb < 2; ++nb)
                mma_f16(c1[mf][nb], a[mf], bf[nb]);
    }

    // combine: gate + dyn from global, store out
    const float* bc = mat ? bbv : bfv;
#pragma unroll
    for (int nb = 0; nb < 2; ++nb) {
        const int cl = wn + nb * 8 + lc * 2;
        const float2 biasC = *(const float2*)(bc + cl);
#pragma unroll
        for (int mf = 0; mf < 2; ++mf) {
#pragma unroll
            for (int h = 0; h < 2; ++h) {
                const int row = r0 + wm + mf * 16 + lr + h * 8;
                const float2 dyn = *(const float2*)(nfeat + (size_t)row * kINPUT + cl);
                const float2 gte = *(const float2*)(g_gate + (size_t)row * 128 + mat * 64 + cl);
                float2 o;
                o.x = (c1[mf][nb][2 * h]     + biasC.x) * dyn.x * gte.x;
                o.y = (c1[mf][nb][2 * h + 1] + biasC.y) * dyn.y * gte.y;
                *(float2*)(out + (size_t)row * 128 + mat * 64 + cl) = o;
            }
        }
    }
}

// ---------------------------------------------------------------------------
extern "C" void kernel_launch(void* const* d_in, const int* in_sizes, int n_in,
                              void* d_out, int out_size) {
    (void)in_sizes; (void)n_in; (void)out_size;
    const float* nfeat = (const float*)d_in[0];
    const float* adjF  = (const float*)d_in[1];
    const float* adjB  = (const float*)d_in[2];
    const float* Wf    = (const float*)d_in[3];
    const float* bfv   = (const float*)d_in[4];
    const float* Wb    = (const float*)d_in[5];
    const float* bbv   = (const float*)d_in[6];
    const float* We    = (const float*)d_in[7];
    const float* be    = (const float*)d_in[8];
    float* out = (float*)d_out;

    static bool attr_set = false;
    if (!attr_set) {
        cudaFuncSetAttribute(gcn_mma_kernel,
                             cudaFuncAttributeMaxDynamicSharedMemorySize, SMEM_GCN);
        cudaFuncSetAttribute(gate_kernel,
                             cudaFuncAttributeMaxDynamicSharedMemorySize, SMEM_GATE);
        cudaFuncSetAttribute(epilogue_mma,
                             cudaFuncAttributeMaxDynamicSharedMemorySize, SMEM_EPI);
        attr_set = true;
    }

    prep_all<<<768, 256>>>(nfeat, Wf, Wb, We);
    gate_kernel<<<kB * kN / 64, 256, SMEM_GATE>>>(be);
    gcn_mma_kernel<<<dim3(kN / BM, kB, 2), 256, SMEM_GCN>>>(adjF, adjB);
    epilogue_mma<<<dim3(kB * kN / 64, 2), 256, SMEM_EPI>>>(nfeat, bfv, bbv, out);
}

// round 13
// speedup vs baseline: 1.1043x; 1.1043x over previous
#include <cuda_runtime.h>
#include <cuda_fp16.h>
#include <cstdint>
#include <cstddef>

// ===========================================================================
// feature_embedding on GB300 (base compute_103: mma.sync fp16 tensor cores).
// Round 13: round-11 structure (best, 54.0us) + MLP-4 prep transpose +
// ldmatrix fragment loads in the epilogue. gcn untouched (at HMMA floor).
//  B=4, N=2048, DEST=64, NET=256, INPUT=448
// ===========================================================================

namespace {
constexpr int kB     = 4;
constexpr int kN     = 2048;
constexpr int kINPUT = 448;
constexpr int BM     = 128;
constexpr int BK     = 64;           // k per iter (4 x m16n8k16)
constexpr int SB     = 3;            // B cp.async stages
constexpr int NUM_K  = kN / BK;      // 32
constexpr int TILE_A16 = BM * BK * 2;            // 16 KB fp16 A tile
constexpr int TILE_B16 = 128 * BK * 2;           // 16 KB fp16 B tile
constexpr int A_REGION = 2 * TILE_A16;           // A double buffer 32 KB
constexpr int SMEM_GCN = A_REGION + SB * TILE_B16;   // 80 KB

// epilogue smem layout (bytes) — 64-row tiles
constexpr int oH  = 0;            // H16 tile  64 x 272B
constexpr int oWc = 17408;        // WcT       64 x 272B
constexpr int oS  = 34816;        // stat16    64 x 528B
constexpr int oWe = 68608;        // WeT slice 64 x 528B
constexpr int SMEM_EPI = 102400;
}

// scratch
__device__ __align__(1024) __half g_Bt    [(size_t)kB * 128 * kN];  // structT fp16
__device__ __align__(1024) __half g_H16   [(size_t)kB * kN * 256];  // [hf|hb] fp16
__device__ __align__(1024) __half g_stat16[(size_t)kB * kN * 256];  // stat fp16
__device__ __align__(256)  __half g_WcT   [2 * 64 * 128];           // [mat][n][k]
__device__ __align__(256)  __half g_WeT   [128 * 256];              // [n][k]

// ---------------------------------------------------------------------------
// helpers
// ---------------------------------------------------------------------------
__device__ __forceinline__ uint32_t smem_u32(const void* p) {
    uint32_t a;
    asm("{ .reg .u64 t; cvta.to.shared.u64 t, %1; cvt.u32.u64 %0, t; }"
        : "=r"(a) : "l"(p));
    return a;
}
__device__ __forceinline__ void cp_async16(uint32_t dst, const void* src) {
    asm volatile("cp.async.cg.shared.global [%0], [%1], 16;"
                 :: "r"(dst), "l"(src) : "memory");
}
__device__ __forceinline__ void cp_commit() {
    asm volatile("cp.async.commit_group;" ::: "memory");
}
template <int N>
__device__ __forceinline__ void cp_wait() {
    asm volatile("cp.async.wait_group %0;" :: "n"(N) : "memory");
}
__device__ __forceinline__ void ldsm_x4(uint32_t r[4], uint32_t addr) {
    asm volatile("ldmatrix.sync.aligned.m8n8.x4.shared.b16 {%0,%1,%2,%3}, [%4];"
                 : "=r"(r[0]), "=r"(r[1]), "=r"(r[2]), "=r"(r[3]) : "r"(addr));
}
__device__ __forceinline__ void sts_v4(uint32_t addr, uint32_t x, uint32_t y,
                                       uint32_t z, uint32_t w) {
    asm volatile("st.shared.v4.b32 [%0], {%1,%2,%3,%4};"
                 :: "r"(addr), "r"(x), "r"(y), "r"(z), "r"(w) : "memory");
}
__device__ __forceinline__ uint32_t pack_h2(float lo, float hi) {
    __half2 h = __floats2half2_rn(lo, hi);
    return *reinterpret_cast<uint32_t*>(&h);
}
__device__ __forceinline__ void mma_f16(float c[4], const uint32_t a[4],
                                        const uint32_t b[2]) {
    asm volatile(
        "mma.sync.aligned.m16n8k16.row.col.f32.f16.f16.f32 "
        "{%0,%1,%2,%3}, {%4,%5,%6,%7}, {%8,%9}, {%0,%1,%2,%3};"
        : "+f"(c[0]), "+f"(c[1]), "+f"(c[2]), "+f"(c[3])
        : "r"(a[0]), "r"(a[1]), "r"(a[2]), "r"(a[3]), "r"(b[0]), "r"(b[1]));
}

// ---------------------------------------------------------------------------
// Prep: blocks [0,256) transpose struct (MLP=4) -> g_Bt fp16;
//       blocks [256,768) convert stat + weights.
// ---------------------------------------------------------------------------
__global__ void __launch_bounds__(256) prep_all(
    const float* __restrict__ nfeat,
    const float* __restrict__ Wf, const float* __restrict__ Wb,
    const float* __restrict__ We) {
    const int bx = blockIdx.x;
    const int tid = threadIdx.x;
    if (bx < 256) {
        // transpose tile: 128 nodes x 32 feats
        __shared__ float s[32][133];
        const int n0 = (bx & 15) * 128;
        const int f0 = ((bx >> 4) & 3) * 32;
        const int b  = bx >> 6;
        float4 x[4];
#pragma unroll
        for (int k = 0; k < 4; ++k) {        // 4 independent float4 loads (MLP=4)
            const int v = tid + 256 * k;     // 0..1023
            const int node = v >> 3;
            const int fq   = v & 7;
            x[k] = *(const float4*)(nfeat +
                (size_t)(b * kN + n0 + node) * kINPUT + 64 + f0 + fq * 4);
        }
#pragma unroll
        for (int k = 0; k < 4; ++k) {
            const int v = tid + 256 * k;
            const int node = v >> 3;
            const int fq   = v & 7;
            s[fq * 4 + 0][node] = x[k].x;
            s[fq * 4 + 1][node] = x[k].y;
            s[fq * 4 + 2][node] = x[k].z;
            s[fq * 4 + 3][node] = x[k].w;
        }
        __syncthreads();
#pragma unroll
        for (int j = 0; j < 4; ++j) {
            const int feat = (tid >> 5) + 8 * j;
            __half* dst = g_Bt + ((size_t)(b * 128 + f0 + feat)) * kN + n0;
#pragma unroll
            for (int cch = 0; cch < 4; ++cch) {
                const int node = (tid & 31) + 32 * cch;
                dst[node] = __float2half_rn(s[feat][node]);
            }
        }
    } else {
        const int t = (bx - 256) * 256 + tid;            // 0..131071
        for (int i = t; i < kB * kN * 64; i += 131072) { // stat fp32 -> fp16
            const int row = i >> 6, c4 = i & 63;
            const float4 v = *(const float4*)(nfeat + (size_t)row * kINPUT + 192 + c4 * 4);
            uint32_t* d = reinterpret_cast<uint32_t*>(g_stat16 + (size_t)row * 256 + c4 * 4);
            d[0] = pack_h2(v.x, v.y);
            d[1] = pack_h2(v.z, v.w);
        }
        if (t < 128 * 256) {      // WeT
            const int n = t >> 8, k = t & 255;
            g_WeT[t] = __float2half_rn(We[k * 128 + n]);
        }
        if (t < 64 * 128) {       // WcT (both mats)
            const int n = t >> 7, k = t & 127;
            g_WcT[t]        = __float2half_rn(Wf[k * 64 + n]);
            g_WcT[8192 + t] = __float2half_rn(Wb[k * 64 + n]);
        }
    }
}

// ---------------------------------------------------------------------------
// Kernel A: H16-tile[128,128] = adj_tile[128,2048] @ structT[128,2048]^T
// (UNCHANGED from round 9/11 — measured at the fallback-HMMA issue floor.)
// ---------------------------------------------------------------------------
__global__ void __launch_bounds__(256, 1) gcn_mma_kernel(
    const float* __restrict__ adjF, const float* __restrict__ adjB) {
    extern __shared__ char smem[];
    const uint32_t sbA = smem_u32(smem);
    const uint32_t sbB = sbA + A_REGION;

    const int tid  = threadIdx.x;
    const int warp = tid >> 5;
    const int lane = tid & 31;
    const int lr   = lane >> 2;
    const int lc   = lane & 3;
    const int wm   = (warp >> 2) * 64;
    const int wn   = (warp & 3) * 32;

    const int m0  = blockIdx.x * BM;
    const int b   = blockIdx.y;
    const int mat = blockIdx.z;
    const float* adj = mat ? adjB : adjF;

    const float*  srcA[4];
    const __half* srcB[4];
    uint32_t dstAB[4];
#pragma unroll
    for (int q = 0; q < 4; ++q) {
        const int idx = q * 256 + tid;
        const int row = idx >> 3;
        const int vec = idx & 7;
        srcA[q] = adj  + ((size_t)(b * kN + m0 + row)) * kN + vec * 8;
        srcB[q] = g_Bt + ((size_t)(b * 128 + row)) * kN + vec * 8;
        dstAB[q] = (uint32_t)(row * 128 + ((vec ^ (row & 7)) << 4));
    }

    const int g  = lane >> 3;
    const int tr = lane & 7;
    uint32_t aLdsm[4];
#pragma unroll
    for (int mf = 0; mf < 4; ++mf) {
        const int row = wm + mf * 16 + (g & 1) * 8 + tr;
        aLdsm[mf] = (uint32_t)(row * 128 + (((g >> 1) ^ (row & 7)) << 4));
    }
    uint32_t bLdsm[2];
#pragma unroll
    for (int p = 0; p < 2; ++p) {
        const int row = wn + p * 16 + (g >> 1) * 8 + tr;
        bLdsm[p] = (uint32_t)(row * 128 + (((g & 1) ^ (row & 7)) << 4));
    }

    float c[4][4][4];
#pragma unroll
    for (int mf = 0; mf < 4; ++mf)
#pragma unroll
        for (int nb = 0; nb < 4; ++nb)
#pragma unroll
            for (int r = 0; r < 4; ++r) c[mf][nb][r] = 0.0f;

#pragma unroll
    for (int s = 0; s < SB - 1; ++s) {
#pragma unroll
        for (int q = 0; q < 4; ++q)
            cp_async16(sbB + s * TILE_B16 + dstAB[q], srcB[q] + s * BK);
        cp_commit();
    }
    float4 rA[4][2];
#pragma unroll
    for (int q = 0; q < 4; ++q) {
        rA[q][0] = *(const float4*)(srcA[q]);
        rA[q][1] = *(const float4*)(srcA[q] + 4);
    }
#pragma unroll
    for (int q = 0; q < 4; ++q)
        sts_v4(sbA + dstAB[q],
               pack_h2(rA[q][0].x, rA[q][0].y), pack_h2(rA[q][0].z, rA[q][0].w),
               pack_h2(rA[q][1].x, rA[q][1].y), pack_h2(rA[q][1].z, rA[q][1].w));
#pragma unroll
    for (int q = 0; q < 4; ++q) {
        rA[q][0] = *(const float4*)(srcA[q] + BK);
        rA[q][1] = *(const float4*)(srcA[q] + BK + 4);
    }

    for (int i = 0; i < NUM_K; ++i) {
        cp_wait<SB - 2>();
        __syncthreads();

        if (i + 1 < NUM_K) {
            const uint32_t aNext = sbA + (uint32_t)(((i + 1) & 1) * TILE_A16);
#pragma unroll
            for (int q = 0; q < 4; ++q)
                sts_v4(aNext + dstAB[q],
                       pack_h2(rA[q][0].x, rA[q][0].y), pack_h2(rA[q][0].z, rA[q][0].w),
                       pack_h2(rA[q][1].x, rA[q][1].y), pack_h2(rA[q][1].z, rA[q][1].w));
        }
        if (i + 2 < NUM_K) {
            const int kof = (i + 2) * BK;
#pragma unroll
            for (int q = 0; q < 4; ++q) {
                rA[q][0] = *(const float4*)(srcA[q] + kof);
                rA[q][1] = *(const float4*)(srcA[q] + kof + 4);
            }
#pragma unroll
            for (int q = 0; q < 4; ++q)
                cp_async16(sbB + ((i + 2) % SB) * TILE_B16 + dstAB[q],
                           srcB[q] + kof);
        }
        cp_commit();

        const uint32_t aSlot = sbA + (uint32_t)((i & 1) * TILE_A16);
        const uint32_t bSlot = sbB + (uint32_t)((i % SB) * TILE_B16);
#pragma unroll
        for (int ks = 0; ks < 4; ++ks) {
            const uint32_t kx = (uint32_t)(ks << 5);
            uint32_t a[4][4];
#pragma unroll
            for (int mf = 0; mf < 4; ++mf)
                ldsm_x4(a[mf], (aSlot + aLdsm[mf]) ^ kx);
            uint32_t bf[4][4];
#pragma unroll
            for (int p = 0; p < 2; ++p)
                ldsm_x4(bf[p * 2], (bSlot + bLdsm[p]) ^ kx);
#pragma unroll
            for (int mf = 0; mf < 4; ++mf) {
#pragma unroll
                for (int p = 0; p < 2; ++p) {
                    mma_f16(c[mf][p * 2],     a[mf], &bf[p * 2][0]);
                    mma_f16(c[mf][p * 2 + 1], a[mf], &bf[p * 2][2]);
                }
            }
        }
    }

#pragma unroll
    for (int mf = 0; mf < 4; ++mf) {
        const int row = m0 + wm + mf * 16 + lr;
        const size_t base = ((size_t)(b * kN + row)) * 256 + mat * 128;
#pragma unroll
        for (int nb = 0; nb < 4; ++nb) {
            const int col = wn + nb * 8 + lc * 2;
            *reinterpret_cast<uint32_t*>(g_H16 + base + col) =
                pack_h2(c[mf][nb][0], c[mf][nb][1]);
            *reinterpret_cast<uint32_t*>(g_H16 + base + 8 * 256 + col) =
                pack_h2(c[mf][nb][2], c[mf][nb][3]);
        }
    }
}

// ---------------------------------------------------------------------------
// Kernel B: mma epilogue. grid (128, 2) = (row-tile of 64, mat); 256 threads;
// 2 CTAs/SM. Two pipelined cp.async groups; fragment loads via ldmatrix
// (row strides 272/528 B are bank-quad disjoint per 8x8 matrix).
//   group1 = H16 + WcT  -> wait<1> -> gemm1 (code) overlaps group2 transfer
//   group2 = stat + WeT -> wait<0> -> gemm2 (gate), combine, store.
// ---------------------------------------------------------------------------
__global__ void __launch_bounds__(256, 2) epilogue_mma(
    const float* __restrict__ nfeat,
    const float* __restrict__ bfv, const float* __restrict__ bbv,
    const float* __restrict__ be,  float* __restrict__ out) {
    extern __shared__ char smem[];
    const uint32_t sb = smem_u32(smem);

    const int tid  = threadIdx.x;
    const int warp = tid >> 5;
    const int lane = tid & 31;
    const int lr   = lane >> 2;
    const int lc   = lane & 3;
    const int wm   = (warp >> 2) * 32;   // rows 0 | 32
    const int wn   = (warp & 3) * 16;    // cols (0..63)

    const int r0  = blockIdx.x * 64;     // global row in [0, 8192)
    const int mat = blockIdx.y;

    // ---- group 1: H16 + WcT ----
    for (int idx = tid; idx < 1024; idx += 256) {        // H16 slice 64x128
        const int row = idx >> 4, v = idx & 15;
        cp_async16(sb + oH + row * 272 + v * 16,
                   g_H16 + ((size_t)(r0 + row)) * 256 + mat * 128 + v * 8);
    }
    for (int idx = tid; idx < 1024; idx += 256) {        // WcT 64x128
        const int row = idx >> 4, v = idx & 15;
        cp_async16(sb + oWc + row * 272 + v * 16,
                   g_WcT + mat * 64 * 128 + row * 128 + v * 8);
    }
    cp_commit();
    // ---- group 2: stat16 + WeT ----
    for (int idx = tid; idx < 2048; idx += 256) {        // stat16 64x256
        const int row = idx >> 5, v = idx & 31;
        cp_async16(sb + oS + row * 528 + v * 16,
                   g_stat16 + ((size_t)(r0 + row)) * 256 + v * 8);
    }
    for (int idx = tid; idx < 2048; idx += 256) {        // WeT slice 64x256
        const int row = idx >> 5, v = idx & 31;
        cp_async16(sb + oWe + row * 528 + v * 16,
                   g_WeT + ((size_t)(mat * 64 + row)) * 256 + v * 8);
    }
    cp_commit();

    cp_wait<1>();             // group 1 done; group 2 still in flight
    __syncthreads();

    // ldmatrix geometry (same mapping as gcn kernel, no XOR swizzle needed —
    // row strides 272/528 B put the 8 rows of each 8x8 matrix on disjoint
    // bank quads).
    const int g   = lane >> 3;           // matrix group 0..3
    const int tr2 = lane & 7;            // row within matrix

    // gemm1 (stride 272): A rows = H tile, B rows = WcT
    uint32_t aE1[2];
#pragma unroll
    for (int mf = 0; mf < 2; ++mf)
        aE1[mf] = sb + oH + (uint32_t)((wm + mf * 16 + (g & 1) * 8 + tr2) * 272)
                 + (uint32_t)((g >> 1) << 4);
    const uint32_t bE1 = sb + oWc + (uint32_t)((wn + (g >> 1) * 8 + tr2) * 272)
                 + (uint32_t)((g & 1) << 4);

    // ---- gemm1: code (K = 128) — overlaps group-2 transfer ----
    float c1[2][2][4];
#pragma unroll
    for (int mf = 0; mf < 2; ++mf)
#pragma unroll
        for (int nb = 0; nb < 2; ++nb)
#pragma unroll
            for (int r = 0; r < 4; ++r) c1[mf][nb][r] = 0.0f;
#pragma unroll
    for (int ks = 0; ks < 8; ++ks) {
        const uint32_t ko = (uint32_t)(ks * 32);
        uint32_t a[2][4];
#pragma unroll
        for (int mf = 0; mf < 2; ++mf)
            ldsm_x4(a[mf], aE1[mf] + ko);
        uint32_t bf[4];
        ldsm_x4(bf, bE1 + ko);
        // bf = {b(nb0,k0), b(nb0,k8), b(nb1,k0), b(nb1,k8)}
#pragma unroll
        for (int mf = 0; mf < 2; ++mf) {
            mma_f16(c1[mf][0], a[mf], &bf[0]);
            mma_f16(c1[mf][1], a[mf], &bf[2]);
        }
    }

    cp_wait<0>();             // group 2 done
    __syncthreads();

    // gemm2 (stride 528): A rows = stat tile, B rows = WeT slice
    uint32_t aE2[2];
#pragma unroll
    for (int mf = 0; mf < 2; ++mf)
        aE2[mf] = sb + oS + (uint32_t)((wm + mf * 16 + (g & 1) * 8 + tr2) * 528)
                 + (uint32_t)((g >> 1) << 4);
    const uint32_t bE2 = sb + oWe + (uint32_t)((wn + (g >> 1) * 8 + tr2) * 528)
                 + (uint32_t)((g & 1) << 4);

    // ---- gemm2: gate (K = 256) ----
    float c2[2][2][4];
#pragma unroll
    for (int mf = 0; mf < 2; ++mf)
#pragma unroll
        for (int nb = 0; nb < 2; ++nb)
#pragma unroll
            for (int r = 0; r < 4; ++r) c2[mf][nb][r] = 0.0f;
#pragma unroll
    for (int ks = 0; ks < 16; ++ks) {
        const uint32_t ko = (uint32_t)(ks * 32);
        uint32_t a[2][4];
#pragma unroll
        for (int mf = 0; mf < 2; ++mf)
            ldsm_x4(a[mf], aE2[mf] + ko);
        uint32_t bf[4];
        ldsm_x4(bf, bE2 + ko);
#pragma unroll
        for (int mf = 0; mf < 2; ++mf) {
            mma_f16(c2[mf][0], a[mf], &bf[0]);
            mma_f16(c2[mf][1], a[mf], &bf[2]);
        }
    }

    // ---- combine + store ----
    const float* bc = mat ? bbv : bfv;
#pragma unroll
    for (int nb = 0; nb < 2; ++nb) {
        const int cl = wn + nb * 8 + lc * 2;
        const float2 biasC = *(const float2*)(bc + cl);
        const float2 biasG = *(const float2*)(be + mat * 64 + cl);
#pragma unroll
        for (int mf = 0; mf < 2; ++mf) {
#pragma unroll
            for (int h = 0; h < 2; ++h) {
                const int row = r0 + wm + mf * 16 + lr + h * 8;
                const float2 dyn = *(const float2*)(nfeat + (size_t)row * kINPUT + cl);
                const float g0 = 1.0f / (1.0f + __expf(-(c2[mf][nb][2 * h]     + biasG.x)));
                const float g1 = 1.0f / (1.0f + __expf(-(c2[mf][nb][2 * h + 1] + biasG.y)));
                float2 o;
                o.x = (c1[mf][nb][2 * h]     + biasC.x) * dyn.x * g0;
                o.y = (c1[mf][nb][2 * h + 1] + biasC.y) * dyn.y * g1;
                *(float2*)(out + (size_t)row * 128 + mat * 64 + cl) = o;
            }
        }
    }
}

// ---------------------------------------------------------------------------
extern "C" void kernel_launch(void* const* d_in, const int* in_sizes, int n_in,
                              void* d_out, int out_size) {
    (void)in_sizes; (void)n_in; (void)out_size;
    const float* nfeat = (const float*)d_in[0];
    const float* adjF  = (const float*)d_in[1];
    const float* adjB  = (const float*)d_in[2];
    const float* Wf    = (const float*)d_in[3];
    const float* bfv   = (const float*)d_in[4];
    const float* Wb    = (const float*)d_in[5];
    const float* bbv   = (const float*)d_in[6];
    const float* We    = (const float*)d_in[7];
    const float* be    = (const float*)d_in[8];
    float* out = (float*)d_out;

    static bool attr_set = false;
    if (!attr_set) {
        cudaFuncSetAttribute(gcn_mma_kernel,
                             cudaFuncAttributeMaxDynamicSharedMemorySize, SMEM_GCN);
        cudaFuncSetAttribute(epilogue_mma,
                             cudaFuncAttributeMaxDynamicSharedMemorySize, SMEM_EPI);
        attr_set = true;
    }

    prep_all<<<768, 256>>>(nfeat, Wf, Wb, We);
    gcn_mma_kernel<<<dim3(kN / BM, kB, 2), 256, SMEM_GCN>>>(adjF, adjB);
    epilogue_mma<<<dim3(kB * kN / 64, 2), 256, SMEM_EPI>>>(nfeat, bfv, bbv, be, out);
}